// round 4
// baseline (speedup 1.0000x reference)
#include <cuda_runtime.h>
#include <cuda_fp16.h>
#include <cstdint>

// Problem shape (fixed by dataset): out[M,N] = x[M,K] @ sign(w[K,N]) + b[N]
#define GM_M 8192
#define GM_K 4096
#define GM_N 4096

// Scratch (allocation-free rule: __device__ globals)
__device__ __align__(256) __half g_xh[(size_t)GM_M * GM_K];  // x in fp16, row-major [M,K]
__device__ __align__(256) __half g_wh[(size_t)GM_N * GM_K];  // sign(w) in fp16, K-major [N,K]

// ---------------------------------------------------------------------------
// PTX helpers (base sm_103 target safe: cp.async / ldmatrix / mma.sync only)
// ---------------------------------------------------------------------------
__device__ __forceinline__ uint32_t smem_u32(const void* p) {
    uint32_t a;
    asm("{ .reg .u64 t; cvta.to.shared.u64 t, %1; cvt.u32.u64 %0, t; }" : "=r"(a) : "l"(p));
    return a;
}

__device__ __forceinline__ void cp_async16(uint32_t dst, const void* src) {
    asm volatile("cp.async.cg.shared.global [%0], [%1], 16;" :: "r"(dst), "l"(src));
}
__device__ __forceinline__ void cp_commit() {
    asm volatile("cp.async.commit_group;");
}
template <int N>
__device__ __forceinline__ void cp_wait() {
    asm volatile("cp.async.wait_group %0;" :: "n"(N));
}

__device__ __forceinline__ void ldsm_x4(uint32_t& r0, uint32_t& r1, uint32_t& r2, uint32_t& r3,
                                        uint32_t addr) {
    asm volatile("ldmatrix.sync.aligned.m8n8.x4.shared.b16 {%0,%1,%2,%3}, [%4];"
                 : "=r"(r0), "=r"(r1), "=r"(r2), "=r"(r3) : "r"(addr));
}

__device__ __forceinline__ void mma_16816(float& c0, float& c1, float& c2, float& c3,
                                          uint32_t a0, uint32_t a1, uint32_t a2, uint32_t a3,
                                          uint32_t b0, uint32_t b1) {
    asm volatile(
        "mma.sync.aligned.m16n8k16.row.col.f32.f16.f16.f32 "
        "{%0,%1,%2,%3}, {%4,%5,%6,%7}, {%8,%9}, {%0,%1,%2,%3};"
        : "+f"(c0), "+f"(c1), "+f"(c2), "+f"(c3)
        : "r"(a0), "r"(a1), "r"(a2), "r"(a3), "r"(b0), "r"(b1));
}

// Swizzled smem offset for a [rows x 32 fp16] tile stored as 64B rows.
// Chunk index within a 128B pair of rows = (row%2)*4 + (seg ^ ((row>>1)&3)):
// conflict-free for both 8-lane ldmatrix phases and quarter-warp STS.128 phases.
__device__ __forceinline__ uint32_t swz(uint32_t row, uint32_t seg) {
    return row * 64u + ((seg ^ ((row >> 1) & 3u)) * 16u);
}

// ---------------------------------------------------------------------------
// Prep kernel 1: x (fp32) -> g_xh (fp16), vectorized
// ---------------------------------------------------------------------------
__global__ void convert_x_kernel(const float4* __restrict__ x, int n4) {
    __half2* out = reinterpret_cast<__half2*>(g_xh);
    for (int i = blockIdx.x * blockDim.x + threadIdx.x; i < n4; i += gridDim.x * blockDim.x) {
        float4 v = x[i];
        out[2 * i]     = __floats2half2_rn(v.x, v.y);
        out[2 * i + 1] = __floats2half2_rn(v.z, v.w);
    }
}

// ---------------------------------------------------------------------------
// Prep kernel 2: g_wh[n,k] = sign(w[k,n]) as fp16 (tiled transpose)
// block (32, 8), grid (N/32, K/32)
// ---------------------------------------------------------------------------
__global__ void convert_w_kernel(const float* __restrict__ w, int K, int N) {
    __shared__ float tile[32][33];
    int n0 = blockIdx.x * 32, k0 = blockIdx.y * 32;
    int tx = threadIdx.x, ty = threadIdx.y;
#pragma unroll
    for (int j = 0; j < 32; j += 8)
        tile[ty + j][tx] = w[(size_t)(k0 + ty + j) * N + (n0 + tx)];
    __syncthreads();
#pragma unroll
    for (int j = 0; j < 32; j += 8) {
        float v = tile[tx][ty + j];  // = w[k0+tx][n0+ty+j]
        float s = (v > 0.0f) ? 1.0f : ((v < 0.0f) ? -1.0f : 0.0f);
        g_wh[(size_t)(n0 + ty + j) * K + (k0 + tx)] = __float2half_rn(s);
    }
}

// ---------------------------------------------------------------------------
// GEMM: 128x128 CTA tile, BK=32, 4-stage cp.async pipeline, HMMA m16n8k16.
// 8 warps in a 2x4 grid; each warp computes 64x32 (4 m16-tiles x 4 n8-tiles).
// ---------------------------------------------------------------------------
#define BM 128
#define BN 128
#define BK 32
#define STAGES 4
#define A_BYTES (BM * BK * 2)                 // 8 KB
#define B_BYTES (BN * BK * 2)                 // 8 KB
#define STAGE_BYTES (A_BYTES + B_BYTES)       // 16 KB
#define SMEM_DYN (STAGES * STAGE_BYTES + 256)

__device__ __forceinline__ void load_chunk(uint32_t sA, uint32_t sB,
                                           const __half* __restrict__ Abase,
                                           const __half* __restrict__ Bbase,
                                           int K, int tid) {
    // Each tile = 128 rows x 4 segs of 16B = 512 chunks; 256 threads x 2 chunks.
#pragma unroll
    for (int j = 0; j < 2; ++j) {
        int c = tid + j * 256;
        uint32_t row = (uint32_t)c >> 2, seg = (uint32_t)c & 3;
        uint32_t off = swz(row, seg);
        cp_async16(sA + off, (const char*)(Abase + (size_t)row * K) + seg * 16);
        cp_async16(sB + off, (const char*)(Bbase + (size_t)row * K) + seg * 16);
    }
}

__global__ void __launch_bounds__(256, 2)
gemm_bin_kernel(const float* __restrict__ bias, float* __restrict__ out,
                int M, int N, int K) {
    extern __shared__ char dynsmem[];
    const uint32_t smem = (smem_u32(dynsmem) + 255u) & ~255u;

    const int tid = threadIdx.x;
    const int wid = tid >> 5;
    const int lane = tid & 31;
    const int m0 = blockIdx.y * BM;
    const int n0 = blockIdx.x * BN;
    const int warp_m = (wid >> 2) * 64;  // 0 / 64
    const int warp_n = (wid & 3) * 32;   // 0 / 32 / 64 / 96

    const __half* Abase0 = g_xh + (size_t)m0 * K;
    const __half* Bbase0 = g_wh + (size_t)n0 * K;

    float acc[4][4][4];
#pragma unroll
    for (int i = 0; i < 4; ++i)
#pragma unroll
        for (int j = 0; j < 4; ++j)
#pragma unroll
            for (int r = 0; r < 4; ++r) acc[i][j][r] = 0.0f;

    const int nk = K / BK;  // 128

    // Prologue: fill STAGES-1 buffers
#pragma unroll
    for (int s = 0; s < STAGES - 1; ++s) {
        uint32_t base = smem + s * STAGE_BYTES;
        load_chunk(base, base + A_BYTES, Abase0 + s * BK, Bbase0 + s * BK, K, tid);
        cp_commit();
    }

    const int lr = lane & 7;
    const int g  = lane >> 3;

    for (int kt = 0; kt < nk; ++kt) {
        cp_wait<STAGES - 2>();
        __syncthreads();

        // Prefetch chunk kt+STAGES-1 into the buffer consumed at kt-1
        if (kt + STAGES - 1 < nk) {
            uint32_t base = smem + ((kt + STAGES - 1) % STAGES) * STAGE_BYTES;
            load_chunk(base, base + A_BYTES,
                       Abase0 + (kt + STAGES - 1) * BK,
                       Bbase0 + (kt + STAGES - 1) * BK, K, tid);
        }
        cp_commit();  // uniform group accounting

        const uint32_t aBase = smem + (kt % STAGES) * STAGE_BYTES;
        const uint32_t bBase = aBase + A_BYTES;

#pragma unroll
        for (int s = 0; s < 2; ++s) {  // two k16 steps per BK=32 chunk
            const uint32_t sb = s * 2;
            uint32_t a[4][4], b[4][2];

            // A: 4 m16k16 tiles. Lane groups -> quadrants {(r,k0),(r+8,k0),(r,k8),(r+8,k8)}
#pragma unroll
            for (int tm = 0; tm < 4; ++tm) {
                uint32_t row = warp_m + tm * 16 + lr + (g & 1) * 8;
                uint32_t seg = sb + (g >> 1);
                ldsm_x4(a[tm][0], a[tm][1], a[tm][2], a[tm][3], aBase + swz(row, seg));
            }
            // B: 2 n16k16 ldmatrix.x4, each yielding two n8k16 fragments
#pragma unroll
            for (int tb = 0; tb < 2; ++tb) {
                uint32_t row = warp_n + tb * 16 + lr + (g >> 1) * 8;
                uint32_t seg = sb + (g & 1);
                ldsm_x4(b[2 * tb][0], b[2 * tb][1], b[2 * tb + 1][0], b[2 * tb + 1][1],
                        bBase + swz(row, seg));
            }
#pragma unroll
            for (int tm = 0; tm < 4; ++tm)
#pragma unroll
                for (int tn = 0; tn < 4; ++tn)
                    mma_16816(acc[tm][tn][0], acc[tm][tn][1], acc[tm][tn][2], acc[tm][tn][3],
                              a[tm][0], a[tm][1], a[tm][2], a[tm][3],
                              b[tn][0], b[tn][1]);
        }
        __syncthreads();
    }

    // Epilogue: c-fragment (r=lane/4, c=(lane%4)*2) + bias, float2 stores
    const int qr = lane >> 2;
    const int qc = (lane & 3) * 2;
#pragma unroll
    for (int tm = 0; tm < 4; ++tm) {
#pragma unroll
        for (int tn = 0; tn < 4; ++tn) {
            int n = n0 + warp_n + tn * 8 + qc;
            int m = m0 + warp_m + tm * 16 + qr;
            float2 bv = *reinterpret_cast<const float2*>(bias + n);
            float2 v0 = make_float2(acc[tm][tn][0] + bv.x, acc[tm][tn][1] + bv.y);
            float2 v1 = make_float2(acc[tm][tn][2] + bv.x, acc[tm][tn][3] + bv.y);
            *reinterpret_cast<float2*>(out + (size_t)m * N + n) = v0;
            *reinterpret_cast<float2*>(out + (size_t)(m + 8) * N + n) = v1;
        }
    }
}

// ---------------------------------------------------------------------------
// Launch
// ---------------------------------------------------------------------------
extern "C" void kernel_launch(void* const* d_in, const int* in_sizes, int n_in,
                              void* d_out, int out_size) {
    const float* x = (const float*)d_in[0];   // [M, K] fp32
    const float* w = (const float*)d_in[1];   // [K, N] fp32
    const float* b = (const float*)d_in[2];   // [N]    fp32
    float* out = (float*)d_out;               // [M, N] fp32

    const int N = in_sizes[2];                // filters
    const int K = in_sizes[1] / N;            // d_in
    const int M = in_sizes[0] / K;            // n_tokens

    // 1) x -> fp16
    int n4 = (M * K) / 4;
    convert_x_kernel<<<4096, 256>>>(reinterpret_cast<const float4*>(x), n4);

    // 2) sign(w) -> fp16, transposed to [N, K]
    dim3 tgrid(N / 32, K / 32), tblk(32, 8);
    convert_w_kernel<<<tgrid, tblk>>>(w, K, N);

    // 3) HMMA tensor-core GEMM
    cudaFuncSetAttribute(gemm_bin_kernel, cudaFuncAttributeMaxDynamicSharedMemorySize, SMEM_DYN);
    dim3 grid(N / BN, M / BM);
    gemm_bin_kernel<<<grid, 256, SMEM_DYN>>>(b, out, M, N, K);
}

// round 5
// speedup vs baseline: 1.1692x; 1.1692x over previous
#include <cuda_runtime.h>
#include <cuda_fp16.h>
#include <cstdint>

// Problem shape (fixed by dataset): out[M,N] = x[M,K] @ sign(w[K,N]) + b[N]
#define GM_M 8192
#define GM_K 4096
#define GM_N 4096

// Scratch (allocation-free rule: __device__ globals)
__device__ __align__(256) __half g_xh[(size_t)GM_M * GM_K];  // x in fp16, row-major [M,K]
__device__ __align__(256) __half g_wh[(size_t)GM_N * GM_K];  // sign(w) in fp16, K-major [N,K]

// ---------------------------------------------------------------------------
// PTX helpers (base sm_103 target safe: cp.async / ldmatrix / mma.sync only)
// ---------------------------------------------------------------------------
__device__ __forceinline__ uint32_t smem_u32(const void* p) {
    uint32_t a;
    asm("{ .reg .u64 t; cvta.to.shared.u64 t, %1; cvt.u32.u64 %0, t; }" : "=r"(a) : "l"(p));
    return a;
}

__device__ __forceinline__ void cp_async16(uint32_t dst, const void* src) {
    asm volatile("cp.async.cg.shared.global [%0], [%1], 16;" :: "r"(dst), "l"(src));
}
__device__ __forceinline__ void cp_commit() {
    asm volatile("cp.async.commit_group;");
}
template <int N>
__device__ __forceinline__ void cp_wait() {
    asm volatile("cp.async.wait_group %0;" :: "n"(N));
}

__device__ __forceinline__ void ldsm_x4(uint32_t& r0, uint32_t& r1, uint32_t& r2, uint32_t& r3,
                                        uint32_t addr) {
    asm volatile("ldmatrix.sync.aligned.m8n8.x4.shared.b16 {%0,%1,%2,%3}, [%4];"
                 : "=r"(r0), "=r"(r1), "=r"(r2), "=r"(r3) : "r"(addr));
}

__device__ __forceinline__ void mma_16816(float& c0, float& c1, float& c2, float& c3,
                                          uint32_t a0, uint32_t a1, uint32_t a2, uint32_t a3,
                                          uint32_t b0, uint32_t b1) {
    asm volatile(
        "mma.sync.aligned.m16n8k16.row.col.f32.f16.f16.f32 "
        "{%0,%1,%2,%3}, {%4,%5,%6,%7}, {%8,%9}, {%0,%1,%2,%3};"
        : "+f"(c0), "+f"(c1), "+f"(c2), "+f"(c3)
        : "r"(a0), "r"(a1), "r"(a2), "r"(a3), "r"(b0), "r"(b1));
}

// Swizzled smem offset for a [rows x 32 fp16] tile stored as 64B rows.
// Chunk index within a 128B pair of rows = (row%2)*4 + (seg ^ ((row>>1)&3)):
// conflict-free for both 8-lane ldmatrix phases and quarter-warp STS.128 phases.
__device__ __forceinline__ uint32_t swz(uint32_t row, uint32_t seg) {
    return row * 64u + ((seg ^ ((row >> 1) & 3u)) * 16u);
}

// ---------------------------------------------------------------------------
// Prep kernel 1: x (fp32) -> g_xh (fp16), vectorized
// ---------------------------------------------------------------------------
__global__ void convert_x_kernel(const float4* __restrict__ x, int n4) {
    __half2* out = reinterpret_cast<__half2*>(g_xh);
    for (int i = blockIdx.x * blockDim.x + threadIdx.x; i < n4; i += gridDim.x * blockDim.x) {
        float4 v = x[i];
        out[2 * i]     = __floats2half2_rn(v.x, v.y);
        out[2 * i + 1] = __floats2half2_rn(v.z, v.w);
    }
}

// ---------------------------------------------------------------------------
// Prep kernel 2: g_wh[n,k] = sign(w[k,n]) as fp16 (tiled transpose)
// block (32, 8), grid (N/32, K/32)
// ---------------------------------------------------------------------------
__global__ void convert_w_kernel(const float* __restrict__ w, int K, int N) {
    __shared__ float tile[32][33];
    int n0 = blockIdx.x * 32, k0 = blockIdx.y * 32;
    int tx = threadIdx.x, ty = threadIdx.y;
#pragma unroll
    for (int j = 0; j < 32; j += 8)
        tile[ty + j][tx] = w[(size_t)(k0 + ty + j) * N + (n0 + tx)];
    __syncthreads();
#pragma unroll
    for (int j = 0; j < 32; j += 8) {
        float v = tile[tx][ty + j];  // = w[k0+tx][n0+ty+j]
        float s = (v > 0.0f) ? 1.0f : ((v < 0.0f) ? -1.0f : 0.0f);
        g_wh[(size_t)(n0 + ty + j) * K + (k0 + tx)] = __float2half_rn(s);
    }
}

// ---------------------------------------------------------------------------
// GEMM: 128x128 CTA tile, BK=32, 4-stage cp.async pipeline, HMMA m16n8k16.
// 4 warps in a 2x2 grid; each warp computes 64x64 (4 m16-tiles x 8 n8-tiles).
// 64x64 warp tiles double fragment reuse: 128 B of ldmatrix per HMMA (vs 192)
// so the smem crossbar is no longer the binding pipe.
// ---------------------------------------------------------------------------
#define BM 128
#define BN 128
#define BK 32
#define STAGES 4
#define A_BYTES (BM * BK * 2)                 // 8 KB
#define B_BYTES (BN * BK * 2)                 // 8 KB
#define STAGE_BYTES (A_BYTES + B_BYTES)       // 16 KB
#define SMEM_DYN (STAGES * STAGE_BYTES + 256)

__device__ __forceinline__ void load_chunk(uint32_t sA, uint32_t sB,
                                           const __half* __restrict__ Abase,
                                           const __half* __restrict__ Bbase,
                                           int K, int tid) {
    // Each tile = 128 rows x 4 segs of 16B = 512 chunks; 128 threads x 4 chunks.
#pragma unroll
    for (int j = 0; j < 4; ++j) {
        int c = tid + j * 128;
        uint32_t row = (uint32_t)c >> 2, seg = (uint32_t)c & 3;
        uint32_t off = swz(row, seg);
        cp_async16(sA + off, (const char*)(Abase + (size_t)row * K) + seg * 16);
        cp_async16(sB + off, (const char*)(Bbase + (size_t)row * K) + seg * 16);
    }
}

__global__ void __launch_bounds__(128, 2)
gemm_bin_kernel(const float* __restrict__ bias, float* __restrict__ out,
                int M, int N, int K) {
    extern __shared__ char dynsmem[];
    const uint32_t smem = (smem_u32(dynsmem) + 255u) & ~255u;

    const int tid = threadIdx.x;
    const int wid = tid >> 5;
    const int lane = tid & 31;
    const int m0 = blockIdx.y * BM;
    const int n0 = blockIdx.x * BN;
    const int warp_m = (wid >> 1) * 64;  // 0 / 64
    const int warp_n = (wid & 1) * 64;   // 0 / 64

    const __half* Abase0 = g_xh + (size_t)m0 * K;
    const __half* Bbase0 = g_wh + (size_t)n0 * K;

    float acc[4][8][4];
#pragma unroll
    for (int i = 0; i < 4; ++i)
#pragma unroll
        for (int j = 0; j < 8; ++j)
#pragma unroll
            for (int r = 0; r < 4; ++r) acc[i][j][r] = 0.0f;

    const int nk = K / BK;  // 128

    // Prologue: fill STAGES-1 buffers
#pragma unroll
    for (int s = 0; s < STAGES - 1; ++s) {
        uint32_t base = smem + s * STAGE_BYTES;
        load_chunk(base, base + A_BYTES, Abase0 + s * BK, Bbase0 + s * BK, K, tid);
        cp_commit();
    }

    const int lr = lane & 7;
    const int g  = lane >> 3;

    for (int kt = 0; kt < nk; ++kt) {
        cp_wait<STAGES - 2>();
        __syncthreads();  // stage kt ready AND all reads of stage kt-1 finished

        // Prefetch chunk kt+STAGES-1 into the buffer read at kt-1 (free now)
        if (kt + STAGES - 1 < nk) {
            uint32_t base = smem + ((kt + STAGES - 1) % STAGES) * STAGE_BYTES;
            load_chunk(base, base + A_BYTES,
                       Abase0 + (kt + STAGES - 1) * BK,
                       Bbase0 + (kt + STAGES - 1) * BK, K, tid);
        }
        cp_commit();  // uniform group accounting

        const uint32_t aBase = smem + (kt % STAGES) * STAGE_BYTES;
        const uint32_t bBase = aBase + A_BYTES;

#pragma unroll
        for (int s = 0; s < 2; ++s) {  // two k16 steps per BK=32 chunk
            const uint32_t sb = s * 2;
            uint32_t a[4][4], b[8][2];

            // A: 4 m16k16 tiles. Lane groups -> quadrants {(r,k0),(r+8,k0),(r,k8),(r+8,k8)}
#pragma unroll
            for (int tm = 0; tm < 4; ++tm) {
                uint32_t row = warp_m + tm * 16 + lr + (g & 1) * 8;
                uint32_t seg = sb + (g >> 1);
                ldsm_x4(a[tm][0], a[tm][1], a[tm][2], a[tm][3], aBase + swz(row, seg));
            }
            // B: 4 n16k16 ldmatrix.x4, each yielding two n8k16 fragments
#pragma unroll
            for (int tb = 0; tb < 4; ++tb) {
                uint32_t row = warp_n + tb * 16 + lr + (g >> 1) * 8;
                uint32_t seg = sb + (g & 1);
                ldsm_x4(b[2 * tb][0], b[2 * tb][1], b[2 * tb + 1][0], b[2 * tb + 1][1],
                        bBase + swz(row, seg));
            }
#pragma unroll
            for (int tm = 0; tm < 4; ++tm)
#pragma unroll
                for (int tn = 0; tn < 8; ++tn)
                    mma_16816(acc[tm][tn][0], acc[tm][tn][1], acc[tm][tn][2], acc[tm][tn][3],
                              a[tm][0], a[tm][1], a[tm][2], a[tm][3],
                              b[tn][0], b[tn][1]);
        }
        // no trailing sync: top-of-next-iteration sync orders reads vs overwrite
    }

    // Epilogue: c-fragment (r=lane/4, c=(lane%4)*2) + bias, float2 stores
    const int qr = lane >> 2;
    const int qc = (lane & 3) * 2;
#pragma unroll
    for (int tm = 0; tm < 4; ++tm) {
#pragma unroll
        for (int tn = 0; tn < 8; ++tn) {
            int n = n0 + warp_n + tn * 8 + qc;
            int m = m0 + warp_m + tm * 16 + qr;
            float2 bv = *reinterpret_cast<const float2*>(bias + n);
            float2 v0 = make_float2(acc[tm][tn][0] + bv.x, acc[tm][tn][1] + bv.y);
            float2 v1 = make_float2(acc[tm][tn][2] + bv.x, acc[tm][tn][3] + bv.y);
            *reinterpret_cast<float2*>(out + (size_t)m * N + n) = v0;
            *reinterpret_cast<float2*>(out + (size_t)(m + 8) * N + n) = v1;
        }
    }
}

// ---------------------------------------------------------------------------
// Launch
// ---------------------------------------------------------------------------
extern "C" void kernel_launch(void* const* d_in, const int* in_sizes, int n_in,
                              void* d_out, int out_size) {
    const float* x = (const float*)d_in[0];   // [M, K] fp32
    const float* w = (const float*)d_in[1];   // [K, N] fp32
    const float* b = (const float*)d_in[2];   // [N]    fp32
    float* out = (float*)d_out;               // [M, N] fp32

    const int N = in_sizes[2];                // filters
    const int K = in_sizes[1] / N;            // d_in
    const int M = in_sizes[0] / K;            // n_tokens

    // 1) x -> fp16
    int n4 = (M * K) / 4;
    convert_x_kernel<<<4096, 256>>>(reinterpret_cast<const float4*>(x), n4);

    // 2) sign(w) -> fp16, transposed to [N, K]
    dim3 tgrid(N / 32, K / 32), tblk(32, 8);
    convert_w_kernel<<<tgrid, tblk>>>(w, K, N);

    // 3) HMMA tensor-core GEMM
    cudaFuncSetAttribute(gemm_bin_kernel, cudaFuncAttributeMaxDynamicSharedMemorySize, SMEM_DYN);
    dim3 grid(N / BN, M / BM);
    gemm_bin_kernel<<<grid, 128, SMEM_DYN>>>(b, out, M, N, K);
}